// round 14
// baseline (speedup 1.0000x reference)
#include <cuda_runtime.h>
#include <cuda_bf16.h>
#include <cstdint>
#include <math.h>

#define Bv 256
#define Tv 128
#define Dv 512
#define Hv 1024
#define FCv 1024
#define Av 32
#define BT (Bv*Tv)      // 32768
#define G3 (3*Hv)       // 3072
#define NHEAD 128       // padded head output cols
#define SKv 3           // split-K for the step GEMM (slices 384/320/320)
#define GRP 16          // scan steps per overlap group
#define NG  (Tv/GRP)    // 8 groups
#define GROWS (Bv*GRP)  // 4096 rows per group (time-major)

// ---------------- scratch (static device globals; no allocs) ----------------
__device__ __nv_bfloat16 g_xlnhi[(size_t)BT*Dv],  g_xlnlo[(size_t)BT*Dv];
__device__ __nv_bfloat16 g_xhi[(size_t)BT*FCv],   g_xlo[(size_t)BT*FCv];
__device__ float         g_xg[(size_t)BT*G3];          // time-major rows (t*Bv+b)
__device__ __nv_bfloat16 g_hseqhi[(size_t)BT*Hv], g_hseqlo[(size_t)BT*Hv];   // time-major
__device__ __nv_bfloat16 g_featshi[(size_t)BT*Hv],g_featslo[(size_t)BT*Hv];  // time-major
__device__ float         g_h[Bv*Hv];
__device__ float         g_ghp[(size_t)SKv*Bv*G3];   // split-K partials
__device__ __nv_bfloat16 g_hmhi[Bv*Hv], g_hmlo[Bv*Hv];
__device__ float         g_headtmp[(size_t)BT*NHEAD];  // time-major
// split weights
__device__ __nv_bfloat16 g_wfchi[FCv*Dv],  g_wfclo[FCv*Dv];
__device__ __nv_bfloat16 g_wihhi[G3*FCv],  g_wihlo[G3*FCv];
__device__ __nv_bfloat16 g_whhhi[G3*Hv],   g_whhlo[G3*Hv];
__device__ __nv_bfloat16 g_wouthi[Hv*Hv],  g_woutlo[Hv*Hv];
__device__ __nv_bfloat16 g_wheadhi[NHEAD*Hv], g_wheadlo[NHEAD*Hv];
__device__ float         g_bheadp[NHEAD];

// ---------------- helpers ----------------
__device__ __forceinline__ uint32_t smem_u32(const void* p) {
    uint32_t a;
    asm("{ .reg .u64 t; cvta.to.shared.u64 t, %1; cvt.u32.u64 %0, t; }" : "=r"(a) : "l"(p));
    return a;
}
#define CP_ASYNC16(s, g) \
    asm volatile("cp.async.cg.shared.global [%0], [%1], 16;" :: "r"(s), "l"(g) : "memory")
#define CP_COMMIT() asm volatile("cp.async.commit_group;" ::: "memory")
#define CP_WAIT1()  asm volatile("cp.async.wait_group 1;" ::: "memory")

__device__ __forceinline__ void ldsm4(uint32_t* r, uint32_t addr) {
    asm volatile("ldmatrix.sync.aligned.m8n8.x4.shared.b16 {%0,%1,%2,%3}, [%4];"
        : "=r"(r[0]), "=r"(r[1]), "=r"(r[2]), "=r"(r[3]) : "r"(addr));
}
__device__ __forceinline__ void mma_bf16(float* d, const uint32_t* a, const uint32_t* b) {
    asm volatile("mma.sync.aligned.m16n8k16.row.col.f32.bf16.bf16.f32 "
        "{%0,%1,%2,%3}, {%4,%5,%6,%7}, {%8,%9}, {%0,%1,%2,%3};"
        : "+f"(d[0]), "+f"(d[1]), "+f"(d[2]), "+f"(d[3])
        : "r"(a[0]), "r"(a[1]), "r"(a[2]), "r"(a[3]), "r"(b[0]), "r"(b[1]));
}
__device__ __forceinline__ void bsplit(float v, __nv_bfloat16& hi, __nv_bfloat16& lo) {
    hi = __float2bfloat16(v);
    lo = __float2bfloat16(v - __bfloat162float(hi));
}
__device__ __forceinline__ float sigmoidf_fast(float x) {
    return 1.0f / (1.0f + __expf(-x));
}

// ---------------- LayerNorm over D=512, emits bf16 split ----------------
__global__ void ln_kernel(const float* __restrict__ obs,
                          const float* __restrict__ gamma,
                          const float* __restrict__ beta) {
    int row = blockIdx.x;
    int tid = threadIdx.x;             // 128 threads
    const float* o = obs + (size_t)row * Dv;
    float4 vv = *(const float4*)(o + tid * 4);
    float s = vv.x + vv.y + vv.z + vv.w;
    float ss = vv.x * vv.x + vv.y * vv.y + vv.z * vv.z + vv.w * vv.w;
    __shared__ float red0[32], red1[32];
    for (int off = 16; off; off >>= 1) {
        s  += __shfl_xor_sync(0xffffffffu, s,  off);
        ss += __shfl_xor_sync(0xffffffffu, ss, off);
    }
    int warp = tid >> 5, lane = tid & 31;
    if (lane == 0) { red0[warp] = s; red1[warp] = ss; }
    __syncthreads();
    if (warp == 0) {
        s  = (lane < 4) ? red0[lane] : 0.f;
        ss = (lane < 4) ? red1[lane] : 0.f;
        for (int off = 2; off; off >>= 1) {
            s  += __shfl_xor_sync(0xffffffffu, s,  off);
            ss += __shfl_xor_sync(0xffffffffu, ss, off);
        }
        if (lane == 0) { red0[0] = s; red1[0] = ss; }
    }
    __syncthreads();
    float mean = red0[0] * (1.0f / Dv);
    float var  = red1[0] * (1.0f / Dv) - mean * mean;
    float rstd = rsqrtf(var + 1e-5f);
    float vs[4] = {vv.x, vv.y, vv.z, vv.w};
    __nv_bfloat16 his[4], los[4];
#pragma unroll
    for (int i = 0; i < 4; i++) {
        int c = tid * 4 + i;
        float val = (vs[i] - mean) * rstd * gamma[c] + beta[c];
        bsplit(val, his[i], los[i]);
    }
    __nv_bfloat162* ph = (__nv_bfloat162*)(g_xlnhi + (size_t)row * Dv + tid * 4);
    __nv_bfloat162* pl = (__nv_bfloat162*)(g_xlnlo + (size_t)row * Dv + tid * 4);
    __nv_bfloat162 a; a.x = his[0]; a.y = his[1]; ph[0] = a;
    a.x = his[2]; a.y = his[3]; ph[1] = a;
    a.x = los[0]; a.y = los[1]; pl[0] = a;
    a.x = los[2]; a.y = los[3]; pl[1] = a;
}

// ---------------- fp32 -> bf16 hi/lo split (float4 vectorized) ----------------
__global__ void split_w(const float* __restrict__ src, __nv_bfloat16* __restrict__ hi,
                        __nv_bfloat16* __restrict__ lo, int n4) {
    int i = blockIdx.x * blockDim.x + threadIdx.x;
    if (i >= n4) return;
    float4 v = ((const float4*)src)[i];
    __nv_bfloat16 h0, l0, h1, l1, h2, l2, h3, l3;
    bsplit(v.x, h0, l0); bsplit(v.y, h1, l1);
    bsplit(v.z, h2, l2); bsplit(v.w, h3, l3);
    __nv_bfloat162 a;
    __nv_bfloat162* ph = (__nv_bfloat162*)(hi + (size_t)i * 4);
    __nv_bfloat162* pl = (__nv_bfloat162*)(lo + (size_t)i * 4);
    a.x = h0; a.y = h1; ph[0] = a;
    a.x = h2; a.y = h3; ph[1] = a;
    a.x = l0; a.y = l1; pl[0] = a;
    a.x = l2; a.y = l3; pl[1] = a;
}

// ---------------- head weight prep (pad to 128 rows, split) ----------------
__global__ void head_prep(const float* __restrict__ Wm, const float* __restrict__ Wl,
                          const float* __restrict__ bm, const float* __restrict__ bl) {
    int i = blockIdx.x * blockDim.x + threadIdx.x;
    if (i < NHEAD * Hv) {
        int r = i / Hv;
        float v = 0.f;
        if (r < Av) v = Wm[i];
        else if (r < 2 * Av) v = Wl[i - Av * Hv];
        __nv_bfloat16 h, l; bsplit(v, h, l);
        g_wheadhi[i] = h; g_wheadlo[i] = l;
    }
    if (i < NHEAD) {
        float b = 0.f;
        if (i < Av) b = bm[i];
        else if (i < 2 * Av) b = bl[i - Av];
        g_bheadp[i] = b;
    }
}

// ---------------- mma.sync bf16-split GEMM, BK=32, 2-stage, 2 CTAs/SM ----------------
// 2 stages x 40KB = 80KB smem -> 2 independent CTAs per SM whose barriers are
// NOT synchronized: CTA1's MMA body covers CTA0's sync/ldsm head (same-CTA
// warps are barrier-locked in phase, which capped tensor at 58% in R8-R13).
// Register budget <=128 (launch_bounds 256,2): acc 64 + B-frags 16 +
// A-frag stream (2-deep over mf) 16 + misc.
#define ROWB    80u          // bytes per smem row (64B data + 16B pad)
#define STG_MAT 10240u       // 128 rows * 80B
#define STG_SZ  40960u       // 4 matrices
#define MG_SMEM (2 * 40960)  // 2 stages = 80KB

template<int EPI, int PERM, int UNEV, int GDS>
__global__ void __launch_bounds__(256, 2) mgemm(
    int K, int KtileArg, int rowOff,
    const __nv_bfloat16* __restrict__ Ahi, const __nv_bfloat16* __restrict__ Alo,
    const __nv_bfloat16* __restrict__ Bhi, const __nv_bfloat16* __restrict__ Blo,
    const float* __restrict__ bias,
    float* __restrict__ Cp, int ldc, size_t partStride,
    __nv_bfloat16* __restrict__ Chi, __nv_bfloat16* __restrict__ Clo)
{
    extern __shared__ char smem[];
#if __CUDA_ARCH__ >= 900
    if (GDS) cudaGridDependencySynchronize();
#endif
    const uint32_t sb = smem_u32(smem);
    const int tid = threadIdx.x;
    const int wid = tid >> 5, lane = tid & 31;
    const int bm0 = rowOff + blockIdx.y * 128, bn0 = blockIdx.x * 128;
    int kz0, Ktile;
    if (UNEV) {
        kz0 = (blockIdx.z == 0) ? 0 : (384 + (blockIdx.z - 1) * 320);
        Ktile = (blockIdx.z == 0) ? 384 : 320;
    } else {
        kz0 = blockIdx.z * KtileArg;
        Ktile = KtileArg;
    }
    const int nk = Ktile >> 5;

    // loaders (256 threads): row pair (grow, grow+64), chunk gch of 4x16B per 64B row
    const int grow = tid >> 2, gch = tid & 3;
    const int r0 = bm0 + grow, r1 = bm0 + grow + 64;
    const int a0 = PERM ? (((r0 & 255) << 7) + (r0 >> 8)) : r0;
    const int a1 = PERM ? (((r1 & 255) << 7) + (r1 >> 8)) : r1;
    const __nv_bfloat16* gp[4][2];
    gp[0][0] = Ahi + (size_t)a0 * K + kz0 + gch * 8;
    gp[0][1] = Ahi + (size_t)a1 * K + kz0 + gch * 8;
    gp[1][0] = Alo + (size_t)a0 * K + kz0 + gch * 8;
    gp[1][1] = Alo + (size_t)a1 * K + kz0 + gch * 8;
    gp[2][0] = Bhi + (size_t)(bn0 + grow) * K + kz0 + gch * 8;
    gp[2][1] = Bhi + (size_t)(bn0 + grow + 64) * K + kz0 + gch * 8;
    gp[3][0] = Blo + (size_t)(bn0 + grow) * K + kz0 + gch * 8;
    gp[3][1] = Blo + (size_t)(bn0 + grow + 64) * K + kz0 + gch * 8;
    const uint32_t sd0 = sb + (uint32_t)grow * ROWB + (uint32_t)gch * 16u;
    const uint32_t sd1 = sd0 + 64u * ROWB;

    // prologue: issue stages 0,1
#pragma unroll
    for (int it = 0; it < 2; it++) {
        uint32_t s0 = sd0 + (uint32_t)it * STG_SZ;
        uint32_t s1 = sd1 + (uint32_t)it * STG_SZ;
        size_t ko = (size_t)it * 32;
#pragma unroll
        for (int m = 0; m < 4; m++) {
            CP_ASYNC16(s0 + m * STG_MAT, gp[m][0] + ko);
            CP_ASYNC16(s1 + m * STG_MAT, gp[m][1] + ko);
        }
        CP_COMMIT();
    }

    // warp tiling: 2x4 warp grid, 64x32 per warp
    const int warpM = (wid & 1) * 64;
    const int warpN = (wid >> 1) * 32;
    const uint32_t aoff = (uint32_t)(warpM + (lane & 15)) * ROWB + (uint32_t)(lane >> 4) * 16u;
    const uint32_t boff = 2u * STG_MAT +
        (uint32_t)(warpN + ((lane >> 4) << 3) + (lane & 7)) * ROWB +
        (uint32_t)((lane >> 3) & 1) * 16u;

    float acc[4][4][4];
#pragma unroll
    for (int i = 0; i < 4; i++)
#pragma unroll
        for (int j = 0; j < 4; j++)
#pragma unroll
            for (int q = 0; q < 4; q++) acc[i][j][q] = 0.f;

    for (int it = 0; it < nk; it++) {
        CP_WAIT1();                 // stage it landed (<=1 pending: it+1)
        __syncthreads();
        const uint32_t st = sb + (uint32_t)(it & 1) * STG_SZ;

#pragma unroll
        for (int ks = 0; ks < 2; ks++) {
            const uint32_t kso = (uint32_t)ks * 32u;
            uint32_t bhf[2][4], blf[2][4];
            ldsm4(bhf[0], st + boff + kso);
            ldsm4(bhf[1], st + boff + kso + 16u * ROWB);
            ldsm4(blf[0], st + STG_MAT + boff + kso);
            ldsm4(blf[1], st + STG_MAT + boff + kso + 16u * ROWB);
            // stream A fragments over mf with a 2-deep register buffer
            uint32_t ahf[2][4], alf[2][4];
            ldsm4(ahf[0], st + aoff + kso);
            ldsm4(alf[0], st + STG_MAT + aoff + kso);
#pragma unroll
            for (int mf = 0; mf < 4; mf++) {
                const int cur = mf & 1, nxt = cur ^ 1;
                if (mf < 3) {
                    ldsm4(ahf[nxt], st + aoff + kso + (uint32_t)(mf + 1) * (16u * ROWB));
                    ldsm4(alf[nxt], st + STG_MAT + aoff + kso + (uint32_t)(mf + 1) * (16u * ROWB));
                }
#pragma unroll
                for (int nf = 0; nf < 4; nf++) {
                    const int p = nf >> 1, h2 = (nf & 1) * 2;
                    mma_bf16(acc[mf][nf], ahf[cur], &bhf[p][h2]);
                    mma_bf16(acc[mf][nf], ahf[cur], &blf[p][h2]);
                    mma_bf16(acc[mf][nf], alf[cur], &bhf[p][h2]);
                }
            }
        }

        __syncthreads();            // all warps done reading buf it&1
        if (it + 2 < nk) {
            uint32_t s0 = sd0 + (uint32_t)(it & 1) * STG_SZ;
            uint32_t s1 = sd1 + (uint32_t)(it & 1) * STG_SZ;
            size_t ko = (size_t)(it + 2) * 32;
#pragma unroll
            for (int m = 0; m < 4; m++) {
                CP_ASYNC16(s0 + m * STG_MAT, gp[m][0] + ko);
                CP_ASYNC16(s1 + m * STG_MAT, gp[m][1] + ko);
            }
        }
        CP_COMMIT();
    }

    // ---- epilogue ----
    const int r = lane >> 2, c2 = (lane & 3) * 2;
#pragma unroll
    for (int mf = 0; mf < 4; mf++) {
#pragma unroll
        for (int nf = 0; nf < 4; nf++) {
            const int row0 = bm0 + warpM + mf * 16 + r;
            const int col  = bn0 + warpN + nf * 8 + c2;
            float b0 = 0.f, b1 = 0.f;
            if (bias != nullptr && blockIdx.z == 0) { b0 = bias[col]; b1 = bias[col + 1]; }
            float v00 = acc[mf][nf][0] + b0, v01 = acc[mf][nf][1] + b1;
            float v10 = acc[mf][nf][2] + b0, v11 = acc[mf][nf][3] + b1;
            if (EPI == 2) {
                v00 = fmaxf(v00, 0.f); v01 = fmaxf(v01, 0.f);
                v10 = fmaxf(v10, 0.f); v11 = fmaxf(v11, 0.f);
                __nv_bfloat16 h0, l0, h1, l1;
                bsplit(v00, h0, l0); bsplit(v01, h1, l1);
                __nv_bfloat162 th; th.x = h0; th.y = h1;
                __nv_bfloat162 tl; tl.x = l0; tl.y = l1;
                *(__nv_bfloat162*)(Chi + (size_t)row0 * ldc + col) = th;
                *(__nv_bfloat162*)(Clo + (size_t)row0 * ldc + col) = tl;
                bsplit(v10, h0, l0); bsplit(v11, h1, l1);
                th.x = h0; th.y = h1; tl.x = l0; tl.y = l1;
                *(__nv_bfloat162*)(Chi + (size_t)(row0 + 8) * ldc + col) = th;
                *(__nv_bfloat162*)(Clo + (size_t)(row0 + 8) * ldc + col) = tl;
            } else {
                float* Co = Cp + blockIdx.z * partStride;
                *(float2*)(Co + (size_t)row0 * ldc + col)       = make_float2(v00, v01);
                *(float2*)(Co + (size_t)(row0 + 8) * ldc + col) = make_float2(v10, v11);
            }
        }
    }
}

// ---------------- GRU gates: fused split-K reduce + elementwise, float4 ----------------
__global__ void gru_gates4(int t, const int* __restrict__ starts,
                           const float* __restrict__ b_hh) {
#if __CUDA_ARCH__ >= 900
    cudaGridDependencySynchronize();
#endif
    int idx = blockIdx.x * blockDim.x + threadIdx.x;   // 0..Bv*Hv/4-1
    if (idx >= Bv * Hv / 4) return;
    const int e = idx * 4;
    const int b = e >> 10, j = e & 1023;
    const size_t xrow = ((size_t)t * Bv + b) * G3;
    float4 xr = *(const float4*)(g_xg + xrow + j);
    float4 xz = *(const float4*)(g_xg + xrow + Hv + j);
    float4 xn = *(const float4*)(g_xg + xrow + 2 * Hv + j);
    const size_t PS = (size_t)Bv * G3;
    const size_t grow = (size_t)b * G3;
    float4 hr = *(const float4*)(b_hh + j);
    float4 hz = *(const float4*)(b_hh + Hv + j);
    float4 hn = *(const float4*)(b_hh + 2 * Hv + j);
#pragma unroll
    for (int z = 0; z < SKv; z++) {
        float4 p;
        p = *(const float4*)(g_ghp + z * PS + grow + j);
        hr.x += p.x; hr.y += p.y; hr.z += p.z; hr.w += p.w;
        p = *(const float4*)(g_ghp + z * PS + grow + Hv + j);
        hz.x += p.x; hz.y += p.y; hz.z += p.z; hz.w += p.w;
        p = *(const float4*)(g_ghp + z * PS + grow + 2 * Hv + j);
        hn.x += p.x; hn.y += p.y; hn.z += p.z; hn.w += p.w;
    }
    const float st  = (float)starts[b * Tv + t];
    const float km  = 1.0f - st;
    float4 hv = *(const float4*)(g_h + e);
    float xrs[4] = {xr.x, xr.y, xr.z, xr.w};
    float xzs[4] = {xz.x, xz.y, xz.z, xz.w};
    float xns[4] = {xn.x, xn.y, xn.z, xn.w};
    float hrs[4] = {hr.x, hr.y, hr.z, hr.w};
    float hzs[4] = {hz.x, hz.y, hz.z, hz.w};
    float hns[4] = {hn.x, hn.y, hn.z, hn.w};
    float hms[4] = {hv.x * km, hv.y * km, hv.z * km, hv.w * km};
    float hnew[4];
    __nv_bfloat16 sh[4], sl[4];
#pragma unroll
    for (int i = 0; i < 4; i++) {
        float r = sigmoidf_fast(xrs[i] + hrs[i]);
        float z = sigmoidf_fast(xzs[i] + hzs[i]);
        float n = tanhf(xns[i] + r * hns[i]);
        hnew[i] = (1.0f - z) * n + z * hms[i];
        bsplit(hnew[i], sh[i], sl[i]);
    }
    *(float4*)(g_h + e) = make_float4(hnew[0], hnew[1], hnew[2], hnew[3]);
    const size_t srow = ((size_t)t * Bv + b) * Hv + j;
    __nv_bfloat162 p01, p23;
    p01.x = sh[0]; p01.y = sh[1]; p23.x = sh[2]; p23.y = sh[3];
    *(uint2*)(g_hseqhi + srow) = make_uint2(*(uint32_t*)&p01, *(uint32_t*)&p23);
    p01.x = sl[0]; p01.y = sl[1]; p23.x = sl[2]; p23.y = sl[3];
    *(uint2*)(g_hseqlo + srow) = make_uint2(*(uint32_t*)&p01, *(uint32_t*)&p23);
    if (t + 1 < Tv) {
        const float km2 = 1.0f - (float)starts[b * Tv + t + 1];
        __nv_bfloat16 mh[4], ml[4];
#pragma unroll
        for (int i = 0; i < 4; i++) bsplit(hnew[i] * km2, mh[i], ml[i]);
        p01.x = mh[0]; p01.y = mh[1]; p23.x = mh[2]; p23.y = mh[3];
        *(uint2*)(g_hmhi + e) = make_uint2(*(uint32_t*)&p01, *(uint32_t*)&p23);
        p01.x = ml[0]; p01.y = ml[1]; p23.x = ml[2]; p23.y = ml[3];
        *(uint2*)(g_hmlo + e) = make_uint2(*(uint32_t*)&p01, *(uint32_t*)&p23);
    }
}

// ---------------- head split + clip (per group, time-major source) ----------------
__global__ void head_split(int rowOff, float* __restrict__ out) {
    int idx = blockIdx.x * blockDim.x + threadIdx.x;   // GROWS*64
    if (idx >= GROWS * 64) return;
    int row = rowOff + (idx >> 6), n = idx & 63;       // time-major row
    int t = row >> 8, b = row & 255;
    float v = g_headtmp[(size_t)row * NHEAD + n];
    if (n < Av) {
        out[((size_t)b * Tv + t) * Av + n] = v;
    } else {
        v = fminf(fmaxf(v, -20.0f), 2.0f);
        out[(size_t)BT * Av + ((size_t)b * Tv + t) * Av + (n - Av)] = v;
    }
}

__global__ void init_h(const float* __restrict__ h0, const int* __restrict__ starts) {
    int i = blockIdx.x * blockDim.x + threadIdx.x;
    if (i >= Bv * Hv) return;
    int b = i >> 10;
    float h = h0[i];
    g_h[i] = h;
    float hm = h * (1.0f - (float)starts[b * Tv]);
    __nv_bfloat16 hh, hl; bsplit(hm, hh, hl);
    g_hmhi[i] = hh; g_hmlo[i] = hl;
}
__global__ void emit_h(float* __restrict__ out) {
    int i = blockIdx.x * blockDim.x + threadIdx.x;
    if (i < Bv * Hv) out[i] = g_h[i];
}

extern "C" void kernel_launch(void* const* d_in, const int* in_sizes, int n_in,
                              void* d_out, int out_size) {
    const float* obs    = (const float*)d_in[0];
    const float* h0     = (const float*)d_in[1];
    const int*   starts = (const int*)  d_in[2];
    const float* gamma  = (const float*)d_in[3];
    const float* beta   = (const float*)d_in[4];
    const float* W_fc   = (const float*)d_in[5];
    const float* b_fc   = (const float*)d_in[6];
    const float* W_ih   = (const float*)d_in[7];
    const float* b_ih   = (const float*)d_in[8];
    const float* W_hh   = (const float*)d_in[9];
    const float* b_hh   = (const float*)d_in[10];
    const float* W_out  = (const float*)d_in[11];
    const float* b_out  = (const float*)d_in[12];
    const float* W_mean = (const float*)d_in[13];
    const float* b_mean = (const float*)d_in[14];
    const float* W_ls   = (const float*)d_in[15];
    const float* b_ls   = (const float*)d_in[16];
    float* out = (float*)d_out;

    static cudaStream_t s1 = nullptr, s2 = nullptr;
    static cudaEvent_t evFC, evPre, evScan, evJoin2;
    static cudaEvent_t evx[NG], evh[NG];
    static bool init_done = false;
    if (!init_done) {
        cudaFuncSetAttribute(mgemm<0, 0, 0, 0>, cudaFuncAttributeMaxDynamicSharedMemorySize, MG_SMEM);
        cudaFuncSetAttribute(mgemm<0, 0, 1, 1>, cudaFuncAttributeMaxDynamicSharedMemorySize, MG_SMEM);
        cudaFuncSetAttribute(mgemm<0, 1, 0, 0>, cudaFuncAttributeMaxDynamicSharedMemorySize, MG_SMEM);
        cudaFuncSetAttribute(mgemm<2, 0, 0, 0>, cudaFuncAttributeMaxDynamicSharedMemorySize, MG_SMEM);
        cudaStreamCreateWithFlags(&s1, cudaStreamNonBlocking);
        cudaStreamCreateWithFlags(&s2, cudaStreamNonBlocking);
        cudaEventCreateWithFlags(&evFC, cudaEventDisableTiming);
        cudaEventCreateWithFlags(&evPre, cudaEventDisableTiming);
        cudaEventCreateWithFlags(&evScan, cudaEventDisableTiming);
        cudaEventCreateWithFlags(&evJoin2, cudaEventDisableTiming);
        for (int g = 0; g < NG; g++) {
            cudaEventCreateWithFlags(&evx[g], cudaEventDisableTiming);
            cudaEventCreateWithFlags(&evh[g], cudaEventDisableTiming);
        }
        init_done = true;
    }

    __nv_bfloat16 *xlnhi, *xlnlo, *xhi, *xlo, *hseqhi, *hseqlo, *featshi, *featslo;
    __nv_bfloat16 *hmhi, *hmlo, *wfchi, *wfclo, *wihhi, *wihlo, *whhhi, *whhlo;
    __nv_bfloat16 *wouthi, *woutlo, *wheadhi, *wheadlo;
    float *xg, *ghp, *headtmp, *bheadp;
    cudaGetSymbolAddress((void**)&xlnhi, g_xlnhi);   cudaGetSymbolAddress((void**)&xlnlo, g_xlnlo);
    cudaGetSymbolAddress((void**)&xhi, g_xhi);       cudaGetSymbolAddress((void**)&xlo, g_xlo);
    cudaGetSymbolAddress((void**)&xg, g_xg);
    cudaGetSymbolAddress((void**)&hseqhi, g_hseqhi); cudaGetSymbolAddress((void**)&hseqlo, g_hseqlo);
    cudaGetSymbolAddress((void**)&featshi, g_featshi); cudaGetSymbolAddress((void**)&featslo, g_featslo);
    cudaGetSymbolAddress((void**)&ghp, g_ghp);
    cudaGetSymbolAddress((void**)&hmhi, g_hmhi);     cudaGetSymbolAddress((void**)&hmlo, g_hmlo);
    cudaGetSymbolAddress((void**)&headtmp, g_headtmp);
    cudaGetSymbolAddress((void**)&wfchi, g_wfchi);   cudaGetSymbolAddress((void**)&wfclo, g_wfclo);
    cudaGetSymbolAddress((void**)&wihhi, g_wihhi);   cudaGetSymbolAddress((void**)&wihlo, g_wihlo);
    cudaGetSymbolAddress((void**)&whhhi, g_whhhi);   cudaGetSymbolAddress((void**)&whhlo, g_whhlo);
    cudaGetSymbolAddress((void**)&wouthi, g_wouthi); cudaGetSymbolAddress((void**)&woutlo, g_woutlo);
    cudaGetSymbolAddress((void**)&wheadhi, g_wheadhi); cudaGetSymbolAddress((void**)&wheadlo, g_wheadlo);
    cudaGetSymbolAddress((void**)&bheadp, g_bheadp);

    const size_t PS = (size_t)Bv * G3;

    // ---- stream 0, deterministic prefix (ncu lands on #4 = FC mgemm) ----
    split_w<<<(FCv * Dv / 4 + 255) / 256, 256>>>(W_fc, wfchi, wfclo, FCv * Dv / 4);     // #1
    split_w<<<(G3 * FCv / 4 + 255) / 256, 256>>>(W_ih, wihhi, wihlo, G3 * FCv / 4);     // #2
    ln_kernel<<<BT, 128>>>(obs, gamma, beta);                                            // #3
    mgemm<2, 0, 0, 0><<<dim3(FCv / 128, BT / 128, 1), 256, MG_SMEM>>>(                   // #4 (ncu)
        Dv, Dv, 0, xlnhi, xlnlo, wfchi, wfclo, b_fc, nullptr, FCv, 0, xhi, xlo);
    cudaEventRecord(evFC, 0);
    split_w<<<(G3 * Hv / 4 + 255) / 256, 256>>>(W_hh, whhhi, whhlo, G3 * Hv / 4);
    init_h<<<(Bv * Hv + 255) / 256, 256>>>(h0, starts);
    cudaEventRecord(evPre, 0);

    // ---- s1: xg production in NG chunks (time-major out, PERM A rows) ----
    cudaStreamWaitEvent(s1, evFC, 0);
    for (int g = 0; g < NG; g++) {
        mgemm<0, 1, 0, 0><<<dim3(G3 / 128, GROWS / 128, 1), 256, MG_SMEM, s1>>>(
            FCv, FCv, g * GROWS, xhi, xlo, wihhi, wihlo, b_ih, xg, G3, 0, nullptr, nullptr);
        cudaEventRecord(evx[g], s1);
    }

    // ---- stream 0: the scan, with PDL on the step pair ----
    cudaLaunchAttribute pssAttr[1];
    pssAttr[0].id = cudaLaunchAttributeProgrammaticStreamSerialization;
    pssAttr[0].val.programmaticStreamSerializationAllowed = 1;

    cudaLaunchConfig_t cfgG = {};
    cfgG.gridDim = dim3(G3 / 128, Bv / 128, SKv);
    cfgG.blockDim = dim3(256, 1, 1);
    cfgG.dynamicSmemBytes = MG_SMEM;
    cfgG.stream = 0;
    cfgG.attrs = pssAttr;
    cfgG.numAttrs = 1;

    cudaLaunchConfig_t cfgE = {};
    cfgE.gridDim = dim3((Bv * Hv / 4 + 255) / 256, 1, 1);
    cfgE.blockDim = dim3(256, 1, 1);
    cfgE.dynamicSmemBytes = 0;
    cfgE.stream = 0;
    cfgE.attrs = pssAttr;
    cfgE.numAttrs = 1;

    for (int g = 0; g < NG; g++) {
        cudaStreamWaitEvent(0, evx[g], 0);
        for (int tt = 0; tt < GRP; tt++) {
            int t = g * GRP + tt;
            cudaLaunchKernelEx(&cfgG, mgemm<0, 0, 1, 1>,
                Hv, 0, 0,
                (const __nv_bfloat16*)hmhi, (const __nv_bfloat16*)hmlo,
                (const __nv_bfloat16*)whhhi, (const __nv_bfloat16*)whhlo,
                (const float*)nullptr, ghp, (int)G3, PS,
                (__nv_bfloat16*)nullptr, (__nv_bfloat16*)nullptr);
            cudaLaunchKernelEx(&cfgE, gru_gates4, t, starts, b_hh);
        }
        cudaEventRecord(evh[g], 0);
    }
    emit_h<<<(Bv * Hv + 255) / 256, 256>>>(out + 2 * (size_t)BT * Av);
    cudaEventRecord(evScan, 0);

    // ---- s2: out-projection + heads per group ----
    split_w<<<(Hv * Hv / 4 + 255) / 256, 256, 0, s2>>>(W_out, wouthi, woutlo, Hv * Hv / 4);
    head_prep<<<(NHEAD * Hv + 255) / 256, 256, 0, s2>>>(W_mean, W_ls, b_mean, b_ls);
    for (int g = 0; g < NG; g++) {
        cudaStreamWaitEvent(s2, evh[g], 0);
        mgemm<2, 0, 0, 0><<<dim3(Hv / 128, GROWS / 128, 1), 256, MG_SMEM, s2>>>(
            Hv, Hv, g * GROWS, hseqhi, hseqlo, wouthi, woutlo, b_out, nullptr, Hv, 0, featshi, featslo);
        mgemm<0, 0, 0, 0><<<dim3(1, GROWS / 128, 1), 256, MG_SMEM, s2>>>(
            Hv, Hv, g * GROWS, featshi, featslo, wheadhi, wheadlo, bheadp, headtmp, NHEAD, 0, nullptr, nullptr);
        head_split<<<(GROWS * 64 + 255) / 256, 256, 0, s2>>>(g * GROWS, out);
    }
    cudaEventRecord(evJoin2, s2);

    // ---- join ----
    cudaStreamWaitEvent(0, evScan, 0);
    cudaStreamWaitEvent(0, evJoin2, 0);
}

// round 16
// speedup vs baseline: 1.1011x; 1.1011x over previous
#include <cuda_runtime.h>
#include <cuda_bf16.h>
#include <cstdint>
#include <math.h>

#define Bv 256
#define Tv 128
#define Dv 512
#define Hv 1024
#define FCv 1024
#define Av 32
#define BT (Bv*Tv)      // 32768
#define G3 (3*Hv)       // 3072
#define NHEAD 128       // padded head output cols
#define SKv 3           // split-K for the step GEMM (slices 384/320/320)
#define GRP 16          // scan steps per overlap group
#define NG  (Tv/GRP)    // 8 groups
#define GROWS (Bv*GRP)  // 4096 rows per group (time-major)

// ---------------- scratch (static device globals; no allocs) ----------------
__device__ __nv_bfloat16 g_xlnhi[(size_t)BT*Dv],  g_xlnlo[(size_t)BT*Dv];
__device__ __nv_bfloat16 g_xhi[(size_t)BT*FCv],   g_xlo[(size_t)BT*FCv];
__device__ float         g_xg[(size_t)BT*G3];          // time-major rows (t*Bv+b)
__device__ __nv_bfloat16 g_hseqhi[(size_t)BT*Hv], g_hseqlo[(size_t)BT*Hv];   // time-major
__device__ __nv_bfloat16 g_featshi[(size_t)BT*Hv],g_featslo[(size_t)BT*Hv];  // time-major
__device__ float         g_h[Bv*Hv];
__device__ float         g_ghp[(size_t)SKv*Bv*G3];   // split-K partials
__device__ __nv_bfloat16 g_hmhi[Bv*Hv], g_hmlo[Bv*Hv];
__device__ float         g_headtmp[(size_t)BT*NHEAD];  // time-major
// split weights
__device__ __nv_bfloat16 g_wfchi[FCv*Dv],  g_wfclo[FCv*Dv];
__device__ __nv_bfloat16 g_wihhi[G3*FCv],  g_wihlo[G3*FCv];
__device__ __nv_bfloat16 g_whhhi[G3*Hv],   g_whhlo[G3*Hv];
__device__ __nv_bfloat16 g_wouthi[Hv*Hv],  g_woutlo[Hv*Hv];
__device__ __nv_bfloat16 g_wheadhi[NHEAD*Hv], g_wheadlo[NHEAD*Hv];
__device__ float         g_bheadp[NHEAD];

// ---------------- helpers ----------------
__device__ __forceinline__ uint32_t smem_u32(const void* p) {
    uint32_t a;
    asm("{ .reg .u64 t; cvta.to.shared.u64 t, %1; cvt.u32.u64 %0, t; }" : "=r"(a) : "l"(p));
    return a;
}
#define CP_ASYNC16(s, g) \
    asm volatile("cp.async.cg.shared.global [%0], [%1], 16;" :: "r"(s), "l"(g) : "memory")
#define CP_COMMIT() asm volatile("cp.async.commit_group;" ::: "memory")
#define CP_WAIT2()  asm volatile("cp.async.wait_group 2;" ::: "memory")

__device__ __forceinline__ void ldsm4(uint32_t* r, uint32_t addr) {
    asm volatile("ldmatrix.sync.aligned.m8n8.x4.shared.b16 {%0,%1,%2,%3}, [%4];"
        : "=r"(r[0]), "=r"(r[1]), "=r"(r[2]), "=r"(r[3]) : "r"(addr));
}
__device__ __forceinline__ void mma_bf16(float* d, const uint32_t* a, const uint32_t* b) {
    asm volatile("mma.sync.aligned.m16n8k16.row.col.f32.bf16.bf16.f32 "
        "{%0,%1,%2,%3}, {%4,%5,%6,%7}, {%8,%9}, {%0,%1,%2,%3};"
        : "+f"(d[0]), "+f"(d[1]), "+f"(d[2]), "+f"(d[3])
        : "r"(a[0]), "r"(a[1]), "r"(a[2]), "r"(a[3]), "r"(b[0]), "r"(b[1]));
}
__device__ __forceinline__ void bsplit(float v, __nv_bfloat16& hi, __nv_bfloat16& lo) {
    hi = __float2bfloat16(v);
    lo = __float2bfloat16(v - __bfloat162float(hi));
}
__device__ __forceinline__ float sigmoidf_fast(float x) {
    return 1.0f / (1.0f + __expf(-x));
}
__device__ __forceinline__ float tanhf_fast(float x) {
    float e = __expf(-2.0f * fabsf(x));        // in (0,1], no overflow
    float t = (1.0f - e) / (1.0f + e);
    return copysignf(t, x);
}

// ---------------- LayerNorm over D=512, emits bf16 split ----------------
__global__ void ln_kernel(const float* __restrict__ obs,
                          const float* __restrict__ gamma,
                          const float* __restrict__ beta) {
    int row = blockIdx.x;
    int tid = threadIdx.x;             // 128 threads
    const float* o = obs + (size_t)row * Dv;
    float4 vv = *(const float4*)(o + tid * 4);
    float s = vv.x + vv.y + vv.z + vv.w;
    float ss = vv.x * vv.x + vv.y * vv.y + vv.z * vv.z + vv.w * vv.w;
    __shared__ float red0[32], red1[32];
    for (int off = 16; off; off >>= 1) {
        s  += __shfl_xor_sync(0xffffffffu, s,  off);
        ss += __shfl_xor_sync(0xffffffffu, ss, off);
    }
    int warp = tid >> 5, lane = tid & 31;
    if (lane == 0) { red0[warp] = s; red1[warp] = ss; }
    __syncthreads();
    if (warp == 0) {
        s  = (lane < 4) ? red0[lane] : 0.f;
        ss = (lane < 4) ? red1[lane] : 0.f;
        for (int off = 2; off; off >>= 1) {
            s  += __shfl_xor_sync(0xffffffffu, s,  off);
            ss += __shfl_xor_sync(0xffffffffu, ss, off);
        }
        if (lane == 0) { red0[0] = s; red1[0] = ss; }
    }
    __syncthreads();
    float mean = red0[0] * (1.0f / Dv);
    float var  = red1[0] * (1.0f / Dv) - mean * mean;
    float rstd = rsqrtf(var + 1e-5f);
    float vs[4] = {vv.x, vv.y, vv.z, vv.w};
    __nv_bfloat16 his[4], los[4];
#pragma unroll
    for (int i = 0; i < 4; i++) {
        int c = tid * 4 + i;
        float val = (vs[i] - mean) * rstd * gamma[c] + beta[c];
        bsplit(val, his[i], los[i]);
    }
    __nv_bfloat162* ph = (__nv_bfloat162*)(g_xlnhi + (size_t)row * Dv + tid * 4);
    __nv_bfloat162* pl = (__nv_bfloat162*)(g_xlnlo + (size_t)row * Dv + tid * 4);
    __nv_bfloat162 a; a.x = his[0]; a.y = his[1]; ph[0] = a;
    a.x = his[2]; a.y = his[3]; ph[1] = a;
    a.x = los[0]; a.y = los[1]; pl[0] = a;
    a.x = los[2]; a.y = los[3]; pl[1] = a;
}

// ---------------- fp32 -> bf16 hi/lo split (float4 vectorized) ----------------
__global__ void split_w(const float* __restrict__ src, __nv_bfloat16* __restrict__ hi,
                        __nv_bfloat16* __restrict__ lo, int n4) {
    int i = blockIdx.x * blockDim.x + threadIdx.x;
    if (i >= n4) return;
    float4 v = ((const float4*)src)[i];
    __nv_bfloat16 h0, l0, h1, l1, h2, l2, h3, l3;
    bsplit(v.x, h0, l0); bsplit(v.y, h1, l1);
    bsplit(v.z, h2, l2); bsplit(v.w, h3, l3);
    __nv_bfloat162 a;
    __nv_bfloat162* ph = (__nv_bfloat162*)(hi + (size_t)i * 4);
    __nv_bfloat162* pl = (__nv_bfloat162*)(lo + (size_t)i * 4);
    a.x = h0; a.y = h1; ph[0] = a;
    a.x = h2; a.y = h3; ph[1] = a;
    a.x = l0; a.y = l1; pl[0] = a;
    a.x = l2; a.y = l3; pl[1] = a;
}

// ---------------- head weight prep (pad to 128 rows, split) ----------------
__global__ void head_prep(const float* __restrict__ Wm, const float* __restrict__ Wl,
                          const float* __restrict__ bm, const float* __restrict__ bl) {
    int i = blockIdx.x * blockDim.x + threadIdx.x;
    if (i < NHEAD * Hv) {
        int r = i / Hv;
        float v = 0.f;
        if (r < Av) v = Wm[i];
        else if (r < 2 * Av) v = Wl[i - Av * Hv];
        __nv_bfloat16 h, l; bsplit(v, h, l);
        g_wheadhi[i] = h; g_wheadlo[i] = l;
    }
    if (i < NHEAD) {
        float b = 0.f;
        if (i < Av) b = bm[i];
        else if (i < 2 * Av) b = bl[i - Av];
        g_bheadp[i] = b;
    }
}

// ---------------- mma.sync bf16-split GEMM, BK=32, software-pipelined (R11/R13) ----
#define ROWB    80u          // bytes per smem row (64B data + 16B pad)
#define STG_MAT 10240u       // 128 rows * 80B
#define STG_SZ  40960u       // 4 matrices
#define MG_SMEM (4 * 40960)  // 4 stages = 160KB

#define LD_FRAGS(AH, AL, BH, BL, st, kso) do {                                   \
    _Pragma("unroll")                                                            \
    for (int _mf = 0; _mf < 4; _mf++) {                                          \
        ldsm4(AH[_mf], (st) + aoff + (kso) + _mf * (16u * ROWB));                \
        ldsm4(AL[_mf], (st) + STG_MAT + aoff + (kso) + _mf * (16u * ROWB));      \
    }                                                                            \
    _Pragma("unroll")                                                            \
    for (int _p = 0; _p < 2; _p++) {                                             \
        ldsm4(BH[_p], (st) + boff + (kso) + _p * (16u * ROWB));                  \
        ldsm4(BL[_p], (st) + STG_MAT + boff + (kso) + _p * (16u * ROWB));        \
    }                                                                            \
} while (0)

#define DO_MMAS(AH, AL, BH, BL) do {                                             \
    _Pragma("unroll")                                                            \
    for (int _mf = 0; _mf < 4; _mf++) {                                          \
        _Pragma("unroll")                                                        \
        for (int _nf = 0; _nf < 4; _nf++) {                                      \
            const int _p = _nf >> 1, _h = (_nf & 1) * 2;                         \
            mma_bf16(acc[_mf][_nf], AH[_mf], &BH[_p][_h]);                       \
            mma_bf16(acc[_mf][_nf], AH[_mf], &BL[_p][_h]);                       \
            mma_bf16(acc[_mf][_nf], AL[_mf], &BH[_p][_h]);                       \
        }                                                                        \
    }                                                                            \
} while (0)

template<int EPI, int PERM, int UNEV, int GDS>
__global__ void __launch_bounds__(256, 1) mgemm(
    int K, int KtileArg, int rowOff,
    const __nv_bfloat16* __restrict__ Ahi, const __nv_bfloat16* __restrict__ Alo,
    const __nv_bfloat16* __restrict__ Bhi, const __nv_bfloat16* __restrict__ Blo,
    const float* __restrict__ bias,
    float* __restrict__ Cp, int ldc, size_t partStride,
    __nv_bfloat16* __restrict__ Chi, __nv_bfloat16* __restrict__ Clo)
{
    extern __shared__ char smem[];
#if __CUDA_ARCH__ >= 900
    if (GDS) cudaGridDependencySynchronize();
#endif
    const uint32_t sb = smem_u32(smem);
    const int tid = threadIdx.x;
    const int wid = tid >> 5, lane = tid & 31;
    const int bm0 = rowOff + blockIdx.y * 128, bn0 = blockIdx.x * 128;
    int kz0, Ktile;
    if (UNEV) {
        kz0 = (blockIdx.z == 0) ? 0 : (384 + (blockIdx.z - 1) * 320);
        Ktile = (blockIdx.z == 0) ? 384 : 320;
    } else {
        kz0 = blockIdx.z * KtileArg;
        Ktile = KtileArg;
    }
    const int nk = Ktile >> 5;

    const int grow = tid >> 2, gch = tid & 3;
    const int r0 = bm0 + grow, r1 = bm0 + grow + 64;
    const int a0 = PERM ? (((r0 & 255) << 7) + (r0 >> 8)) : r0;
    const int a1 = PERM ? (((r1 & 255) << 7) + (r1 >> 8)) : r1;
    const __nv_bfloat16* gp[4][2];
    gp[0][0] = Ahi + (size_t)a0 * K + kz0 + gch * 8;
    gp[0][1] = Ahi + (size_t)a1 * K + kz0 + gch * 8;
    gp[1][0] = Alo + (size_t)a0 * K + kz0 + gch * 8;
    gp[1][1] = Alo + (size_t)a1 * K + kz0 + gch * 8;
    gp[2][0] = Bhi + (size_t)(bn0 + grow) * K + kz0 + gch * 8;
    gp[2][1] = Bhi + (size_t)(bn0 + grow + 64) * K + kz0 + gch * 8;
    gp[3][0] = Blo + (size_t)(bn0 + grow) * K + kz0 + gch * 8;
    gp[3][1] = Blo + (size_t)(bn0 + grow + 64) * K + kz0 + gch * 8;
    const uint32_t sd0 = sb + (uint32_t)grow * ROWB + (uint32_t)gch * 16u;
    const uint32_t sd1 = sd0 + 64u * ROWB;

    // prologue: issue stages 0,1,2
#pragma unroll
    for (int it = 0; it < 3; it++) {
        uint32_t s0 = sd0 + (uint32_t)it * STG_SZ;
        uint32_t s1 = sd1 + (uint32_t)it * STG_SZ;
        size_t ko = (size_t)it * 32;
#pragma unroll
        for (int m = 0; m < 4; m++) {
            CP_ASYNC16(s0 + m * STG_MAT, gp[m][0] + ko);
            CP_ASYNC16(s1 + m * STG_MAT, gp[m][1] + ko);
        }
        CP_COMMIT();
    }

    const int warpM = (wid & 1) * 64;
    const int warpN = (wid >> 1) * 32;
    const uint32_t aoff = (uint32_t)(warpM + (lane & 15)) * ROWB + (uint32_t)(lane >> 4) * 16u;
    const uint32_t boff = 2u * STG_MAT +
        (uint32_t)(warpN + ((lane >> 4) << 3) + (lane & 7)) * ROWB +
        (uint32_t)((lane >> 3) & 1) * 16u;

    float acc[4][4][4];
#pragma unroll
    for (int i = 0; i < 4; i++)
#pragma unroll
        for (int j = 0; j < 4; j++)
#pragma unroll
            for (int q = 0; q < 4; q++) acc[i][j][q] = 0.f;

    uint32_t ah0[4][4], al0[4][4], bh0[2][4], bl0[2][4];
    uint32_t ah1[4][4], al1[4][4], bh1[2][4], bl1[2][4];

    CP_WAIT2();
    __syncthreads();
    LD_FRAGS(ah0, al0, bh0, bl0, sb, 0u);

    for (int it = 0; it < nk; it++) {
        const uint32_t st = sb + (uint32_t)(it & 3) * STG_SZ;
        LD_FRAGS(ah1, al1, bh1, bl1, st, 32u);
        DO_MMAS(ah0, al0, bh0, bl0);

        if (it + 3 < nk) {
            uint32_t s0 = sd0 + (uint32_t)((it + 3) & 3) * STG_SZ;
            uint32_t s1 = sd1 + (uint32_t)((it + 3) & 3) * STG_SZ;
            size_t ko = (size_t)(it + 3) * 32;
#pragma unroll
            for (int m = 0; m < 4; m++) {
                CP_ASYNC16(s0 + m * STG_MAT, gp[m][0] + ko);
                CP_ASYNC16(s1 + m * STG_MAT, gp[m][1] + ko);
            }
        }
        CP_COMMIT();
        CP_WAIT2();
        __syncthreads();
        if (it + 1 < nk) {
            const uint32_t st2 = sb + (uint32_t)((it + 1) & 3) * STG_SZ;
            LD_FRAGS(ah0, al0, bh0, bl0, st2, 0u);
        }
        DO_MMAS(ah1, al1, bh1, bl1);
    }

    // ---- epilogue ----
    const int r = lane >> 2, c2 = (lane & 3) * 2;
#pragma unroll
    for (int mf = 0; mf < 4; mf++) {
#pragma unroll
        for (int nf = 0; nf < 4; nf++) {
            const int row0 = bm0 + warpM + mf * 16 + r;
            const int col  = bn0 + warpN + nf * 8 + c2;
            float b0 = 0.f, b1 = 0.f;
            if (bias != nullptr && blockIdx.z == 0) { b0 = bias[col]; b1 = bias[col + 1]; }
            float v00 = acc[mf][nf][0] + b0, v01 = acc[mf][nf][1] + b1;
            float v10 = acc[mf][nf][2] + b0, v11 = acc[mf][nf][3] + b1;
            if (EPI == 2) {
                v00 = fmaxf(v00, 0.f); v01 = fmaxf(v01, 0.f);
                v10 = fmaxf(v10, 0.f); v11 = fmaxf(v11, 0.f);
                __nv_bfloat16 h0, l0, h1, l1;
                bsplit(v00, h0, l0); bsplit(v01, h1, l1);
                __nv_bfloat162 th; th.x = h0; th.y = h1;
                __nv_bfloat162 tl; tl.x = l0; tl.y = l1;
                *(__nv_bfloat162*)(Chi + (size_t)row0 * ldc + col) = th;
                *(__nv_bfloat162*)(Clo + (size_t)row0 * ldc + col) = tl;
                bsplit(v10, h0, l0); bsplit(v11, h1, l1);
                th.x = h0; th.y = h1; tl.x = l0; tl.y = l1;
                *(__nv_bfloat162*)(Chi + (size_t)(row0 + 8) * ldc + col) = th;
                *(__nv_bfloat162*)(Clo + (size_t)(row0 + 8) * ldc + col) = tl;
            } else {
                float* Co = Cp + blockIdx.z * partStride;
                *(float2*)(Co + (size_t)row0 * ldc + col)       = make_float2(v00, v01);
                *(float2*)(Co + (size_t)(row0 + 8) * ldc + col) = make_float2(v10, v11);
            }
        }
    }
}

// ---------------- GRU gates: fused split-K reduce + elementwise, float4 ----------------
__global__ void gru_gates4(int t, const int* __restrict__ starts,
                           const float* __restrict__ b_hh) {
#if __CUDA_ARCH__ >= 900
    cudaGridDependencySynchronize();
#endif
    int idx = blockIdx.x * blockDim.x + threadIdx.x;   // 0..Bv*Hv/4-1
    if (idx >= Bv * Hv / 4) return;
    const int e = idx * 4;
    const int b = e >> 10, j = e & 1023;
    const size_t xrow = ((size_t)t * Bv + b) * G3;
    float4 xr = *(const float4*)(g_xg + xrow + j);
    float4 xz = *(const float4*)(g_xg + xrow + Hv + j);
    float4 xn = *(const float4*)(g_xg + xrow + 2 * Hv + j);
    const size_t PS = (size_t)Bv * G3;
    const size_t grow = (size_t)b * G3;
    float4 hr = *(const float4*)(b_hh + j);
    float4 hz = *(const float4*)(b_hh + Hv + j);
    float4 hn = *(const float4*)(b_hh + 2 * Hv + j);
#pragma unroll
    for (int z = 0; z < SKv; z++) {
        float4 p;
        p = *(const float4*)(g_ghp + z * PS + grow + j);
        hr.x += p.x; hr.y += p.y; hr.z += p.z; hr.w += p.w;
        p = *(const float4*)(g_ghp + z * PS + grow + Hv + j);
        hz.x += p.x; hz.y += p.y; hz.z += p.z; hz.w += p.w;
        p = *(const float4*)(g_ghp + z * PS + grow + 2 * Hv + j);
        hn.x += p.x; hn.y += p.y; hn.z += p.z; hn.w += p.w;
    }
    const float st  = (float)starts[b * Tv + t];
    const float km  = 1.0f - st;
    float4 hv = *(const float4*)(g_h + e);
    float xrs[4] = {xr.x, xr.y, xr.z, xr.w};
    float xzs[4] = {xz.x, xz.y, xz.z, xz.w};
    float xns[4] = {xn.x, xn.y, xn.z, xn.w};
    float hrs[4] = {hr.x, hr.y, hr.z, hr.w};
    float hzs[4] = {hz.x, hz.y, hz.z, hz.w};
    float hns[4] = {hn.x, hn.y, hn.z, hn.w};
    float hms[4] = {hv.x * km, hv.y * km, hv.z * km, hv.w * km};
    float hnew[4];
    __nv_bfloat16 sh[4], sl[4];
#pragma unroll
    for (int i = 0; i < 4; i++) {
        float r = sigmoidf_fast(xrs[i] + hrs[i]);
        float z = sigmoidf_fast(xzs[i] + hzs[i]);
        float n = tanhf_fast(xns[i] + r * hns[i]);
        hnew[i] = (1.0f - z) * n + z * hms[i];
        bsplit(hnew[i], sh[i], sl[i]);
    }
    *(float4*)(g_h + e) = make_float4(hnew[0], hnew[1], hnew[2], hnew[3]);
    const size_t srow = ((size_t)t * Bv + b) * Hv + j;
    __nv_bfloat162 p01, p23;
    p01.x = sh[0]; p01.y = sh[1]; p23.x = sh[2]; p23.y = sh[3];
    *(uint2*)(g_hseqhi + srow) = make_uint2(*(uint32_t*)&p01, *(uint32_t*)&p23);
    p01.x = sl[0]; p01.y = sl[1]; p23.x = sl[2]; p23.y = sl[3];
    *(uint2*)(g_hseqlo + srow) = make_uint2(*(uint32_t*)&p01, *(uint32_t*)&p23);
    if (t + 1 < Tv) {
        const float km2 = 1.0f - (float)starts[b * Tv + t + 1];
        __nv_bfloat16 mh[4], ml[4];
#pragma unroll
        for (int i = 0; i < 4; i++) bsplit(hnew[i] * km2, mh[i], ml[i]);
        p01.x = mh[0]; p01.y = mh[1]; p23.x = mh[2]; p23.y = mh[3];
        *(uint2*)(g_hmhi + e) = make_uint2(*(uint32_t*)&p01, *(uint32_t*)&p23);
        p01.x = ml[0]; p01.y = ml[1]; p23.x = ml[2]; p23.y = ml[3];
        *(uint2*)(g_hmlo + e) = make_uint2(*(uint32_t*)&p01, *(uint32_t*)&p23);
    }
}

// ---------------- head split + clip (per group, time-major source) ----------------
__global__ void head_split(int rowOff, float* __restrict__ out) {
    int idx = blockIdx.x * blockDim.x + threadIdx.x;   // GROWS*64
    if (idx >= GROWS * 64) return;
    int row = rowOff + (idx >> 6), n = idx & 63;       // time-major row
    int t = row >> 8, b = row & 255;
    float v = g_headtmp[(size_t)row * NHEAD + n];
    if (n < Av) {
        out[((size_t)b * Tv + t) * Av + n] = v;
    } else {
        v = fminf(fmaxf(v, -20.0f), 2.0f);
        out[(size_t)BT * Av + ((size_t)b * Tv + t) * Av + (n - Av)] = v;
    }
}

__global__ void init_h(const float* __restrict__ h0, const int* __restrict__ starts) {
    int i = blockIdx.x * blockDim.x + threadIdx.x;
    if (i >= Bv * Hv) return;
    int b = i >> 10;
    float h = h0[i];
    g_h[i] = h;
    float hm = h * (1.0f - (float)starts[b * Tv]);
    __nv_bfloat16 hh, hl; bsplit(hm, hh, hl);
    g_hmhi[i] = hh; g_hmlo[i] = hl;
}
__global__ void emit_h(float* __restrict__ out) {
    int i = blockIdx.x * blockDim.x + threadIdx.x;
    if (i < Bv * Hv) out[i] = g_h[i];
}

extern "C" void kernel_launch(void* const* d_in, const int* in_sizes, int n_in,
                              void* d_out, int out_size) {
    const float* obs    = (const float*)d_in[0];
    const float* h0     = (const float*)d_in[1];
    const int*   starts = (const int*)  d_in[2];
    const float* gamma  = (const float*)d_in[3];
    const float* beta   = (const float*)d_in[4];
    const float* W_fc   = (const float*)d_in[5];
    const float* b_fc   = (const float*)d_in[6];
    const float* W_ih   = (const float*)d_in[7];
    const float* b_ih   = (const float*)d_in[8];
    const float* W_hh   = (const float*)d_in[9];
    const float* b_hh   = (const float*)d_in[10];
    const float* W_out  = (const float*)d_in[11];
    const float* b_out  = (const float*)d_in[12];
    const float* W_mean = (const float*)d_in[13];
    const float* b_mean = (const float*)d_in[14];
    const float* W_ls   = (const float*)d_in[15];
    const float* b_ls   = (const float*)d_in[16];
    float* out = (float*)d_out;

    static cudaStream_t s1 = nullptr, s2 = nullptr;
    static cudaEvent_t evRoot, evFC, evPre, evW, evScan, evJoin2;
    static cudaEvent_t evx[NG], evh[NG];
    static bool init_done = false;
    if (!init_done) {
        cudaFuncSetAttribute(mgemm<0, 0, 0, 0>, cudaFuncAttributeMaxDynamicSharedMemorySize, MG_SMEM);
        cudaFuncSetAttribute(mgemm<0, 0, 1, 1>, cudaFuncAttributeMaxDynamicSharedMemorySize, MG_SMEM);
        cudaFuncSetAttribute(mgemm<0, 1, 0, 0>, cudaFuncAttributeMaxDynamicSharedMemorySize, MG_SMEM);
        cudaFuncSetAttribute(mgemm<2, 0, 0, 0>, cudaFuncAttributeMaxDynamicSharedMemorySize, MG_SMEM);
        cudaStreamCreateWithFlags(&s1, cudaStreamNonBlocking);
        cudaStreamCreateWithFlags(&s2, cudaStreamNonBlocking);
        cudaEventCreateWithFlags(&evRoot, cudaEventDisableTiming);
        cudaEventCreateWithFlags(&evFC, cudaEventDisableTiming);
        cudaEventCreateWithFlags(&evPre, cudaEventDisableTiming);
        cudaEventCreateWithFlags(&evW, cudaEventDisableTiming);
        cudaEventCreateWithFlags(&evScan, cudaEventDisableTiming);
        cudaEventCreateWithFlags(&evJoin2, cudaEventDisableTiming);
        for (int g = 0; g < NG; g++) {
            cudaEventCreateWithFlags(&evx[g], cudaEventDisableTiming);
            cudaEventCreateWithFlags(&evh[g], cudaEventDisableTiming);
        }
        init_done = true;
    }

    __nv_bfloat16 *xlnhi, *xlnlo, *xhi, *xlo, *hseqhi, *hseqlo, *featshi, *featslo;
    __nv_bfloat16 *hmhi, *hmlo, *wfchi, *wfclo, *wihhi, *wihlo, *whhhi, *whhlo;
    __nv_bfloat16 *wouthi, *woutlo, *wheadhi, *wheadlo;
    float *xg, *ghp, *headtmp, *bheadp;
    cudaGetSymbolAddress((void**)&xlnhi, g_xlnhi);   cudaGetSymbolAddress((void**)&xlnlo, g_xlnlo);
    cudaGetSymbolAddress((void**)&xhi, g_xhi);       cudaGetSymbolAddress((void**)&xlo, g_xlo);
    cudaGetSymbolAddress((void**)&xg, g_xg);
    cudaGetSymbolAddress((void**)&hseqhi, g_hseqhi); cudaGetSymbolAddress((void**)&hseqlo, g_hseqlo);
    cudaGetSymbolAddress((void**)&featshi, g_featshi); cudaGetSymbolAddress((void**)&featslo, g_featslo);
    cudaGetSymbolAddress((void**)&ghp, g_ghp);
    cudaGetSymbolAddress((void**)&hmhi, g_hmhi);     cudaGetSymbolAddress((void**)&hmlo, g_hmlo);
    cudaGetSymbolAddress((void**)&headtmp, g_headtmp);
    cudaGetSymbolAddress((void**)&wfchi, g_wfchi);   cudaGetSymbolAddress((void**)&wfclo, g_wfclo);
    cudaGetSymbolAddress((void**)&wihhi, g_wihhi);   cudaGetSymbolAddress((void**)&wihlo, g_wihlo);
    cudaGetSymbolAddress((void**)&whhhi, g_whhhi);   cudaGetSymbolAddress((void**)&whhlo, g_whhlo);
    cudaGetSymbolAddress((void**)&wouthi, g_wouthi); cudaGetSymbolAddress((void**)&woutlo, g_woutlo);
    cudaGetSymbolAddress((void**)&wheadhi, g_wheadhi); cudaGetSymbolAddress((void**)&wheadlo, g_wheadlo);
    cudaGetSymbolAddress((void**)&bheadp, g_bheadp);

    const size_t PS = (size_t)Bv * G3;

    // ---- fork: side streams must branch from the capture-origin stream ----
    cudaEventRecord(evRoot, 0);
    cudaStreamWaitEvent(s1, evRoot, 0);
    cudaStreamWaitEvent(s2, evRoot, 0);

    // ---- s1: W_ih split runs concurrently with LN+FC ----
    split_w<<<(G3 * FCv / 4 + 255) / 256, 256, 0, s1>>>(W_ih, wihhi, wihlo, G3 * FCv / 4);

    // ---- s2: scan prerequisites + late weights, concurrent with LN+FC ----
    split_w<<<(G3 * Hv / 4 + 255) / 256, 256, 0, s2>>>(W_hh, whhhi, whhlo, G3 * Hv / 4);
    init_h<<<(Bv * Hv + 255) / 256, 256, 0, s2>>>(h0, starts);
    cudaEventRecord(evPre, s2);
    split_w<<<(Hv * Hv / 4 + 255) / 256, 256, 0, s2>>>(W_out, wouthi, woutlo, Hv * Hv / 4);
    head_prep<<<(NHEAD * Hv + 255) / 256, 256, 0, s2>>>(W_mean, W_ls, b_mean, b_ls);

    // ---- stream 0: minimal serial prefix ----
    split_w<<<(FCv * Dv / 4 + 255) / 256, 256>>>(W_fc, wfchi, wfclo, FCv * Dv / 4);
    ln_kernel<<<BT, 128>>>(obs, gamma, beta);
    mgemm<2, 0, 0, 0><<<dim3(FCv / 128, BT / 128, 1), 256, MG_SMEM>>>(
        Dv, Dv, 0, xlnhi, xlnlo, wfchi, wfclo, b_fc, nullptr, FCv, 0, xhi, xlo);
    cudaEventRecord(evFC, 0);

    // ---- s1: xg production in NG chunks (time-major out, PERM A rows) ----
    cudaStreamWaitEvent(s1, evFC, 0);
    for (int g = 0; g < NG; g++) {
        mgemm<0, 1, 0, 0><<<dim3(G3 / 128, GROWS / 128, 1), 256, MG_SMEM, s1>>>(
            FCv, FCv, g * GROWS, xhi, xlo, wihhi, wihlo, b_ih, xg, G3, 0, nullptr, nullptr);
        cudaEventRecord(evx[g], s1);
    }

    // ---- stream 0: the scan, with PDL on the step pair ----
    cudaStreamWaitEvent(0, evPre, 0);

    cudaLaunchAttribute pssAttr[1];
    pssAttr[0].id = cudaLaunchAttributeProgrammaticStreamSerialization;
    pssAttr[0].val.programmaticStreamSerializationAllowed = 1;

    cudaLaunchConfig_t cfgG = {};
    cfgG.gridDim = dim3(G3 / 128, Bv / 128, SKv);
    cfgG.blockDim = dim3(256, 1, 1);
    cfgG.dynamicSmemBytes = MG_SMEM;
    cfgG.stream = 0;
    cfgG.attrs = pssAttr;
    cfgG.numAttrs = 1;

    cudaLaunchConfig_t cfgE = {};
    cfgE.gridDim = dim3((Bv * Hv / 4 + 255) / 256, 1, 1);
    cfgE.blockDim = dim3(256, 1, 1);
    cfgE.dynamicSmemBytes = 0;
    cfgE.stream = 0;
    cfgE.attrs = pssAttr;
    cfgE.numAttrs = 1;

    for (int g = 0; g < NG; g++) {
        cudaStreamWaitEvent(0, evx[g], 0);
        for (int tt = 0; tt < GRP; tt++) {
            int t = g * GRP + tt;
            cudaLaunchKernelEx(&cfgG, mgemm<0, 0, 1, 1>,
                Hv, 0, 0,
                (const __nv_bfloat16*)hmhi, (const __nv_bfloat16*)hmlo,
                (const __nv_bfloat16*)whhhi, (const __nv_bfloat16*)whhlo,
                (const float*)nullptr, ghp, (int)G3, PS,
                (__nv_bfloat16*)nullptr, (__nv_bfloat16*)nullptr);
            cudaLaunchKernelEx(&cfgE, gru_gates4, t, starts, b_hh);
        }
        cudaEventRecord(evh[g], 0);
    }
    emit_h<<<(Bv * Hv + 255) / 256, 256>>>(out + 2 * (size_t)BT * Av);
    cudaEventRecord(evScan, 0);

    // ---- s2: out-projection + heads per group ----
    for (int g = 0; g < NG; g++) {
        cudaStreamWaitEvent(s2, evh[g], 0);
        mgemm<2, 0, 0, 0><<<dim3(Hv / 128, GROWS / 128, 1), 256, MG_SMEM, s2>>>(
            Hv, Hv, g * GROWS, hseqhi, hseqlo, wouthi, woutlo, b_out, nullptr, Hv, 0, featshi, featslo);
        mgemm<0, 0, 0, 0><<<dim3(1, GROWS / 128, 1), 256, MG_SMEM, s2>>>(
            Hv, Hv, g * GROWS, featshi, featslo, wheadhi, wheadlo, bheadp, headtmp, NHEAD, 0, nullptr, nullptr);
        head_split<<<(GROWS * 64 + 255) / 256, 256, 0, s2>>>(g * GROWS, out);
    }
    cudaEventRecord(evJoin2, s2);

    // ---- join ----
    cudaStreamWaitEvent(0, evScan, 0);
    cudaStreamWaitEvent(0, evJoin2, 0);
}